// round 5
// baseline (speedup 1.0000x reference)
#include <cuda_runtime.h>
#include <cstdint>
#include <cstddef>

// Problem constants
#define BB      2
#define CC      384
#define DD      32
#define HH      32
#define WW      32
#define HEADS   12
#define HD      32
#define WS      5
#define PADW    2
#define SSP     (DD*HH*WW)           // 32768
#define SCALE   0.17677669529663687f // 32^-0.5

// Scratch (device globals; allocation in kernel_launch is forbidden)
__device__ float g_qkv[(size_t)BB * 3 * CC * SSP];
__device__ float g_attn[(size_t)BB * CC * SSP];

// ---------------------------------------------------------------------------
// SGEMM: C[b][m][n] = sum_k A[m][k]*B[b][k][n] + bias[m]
// 128x128x16 tile, 256 threads, 8x8 microtile, LDG prefetch over compute.
// All dims divide evenly (M in {1152,384}, N=32768, K=384).
// ---------------------------------------------------------------------------
__global__ __launch_bounds__(256)
void sgemm128(const float* __restrict__ A, const float* __restrict__ B,
              const float* __restrict__ bias, float* __restrict__ C,
              int M, int N, int K, size_t strideB, size_t strideC)
{
    __shared__ __align__(16) float As[16][132];   // padded: 2-way store conflict max
    __shared__ __align__(16) float Bs[16][128];

    const float* Bp = B + (size_t)blockIdx.z * strideB;
    float*       Cp = C + (size_t)blockIdx.z * strideC;

    const int tid = threadIdx.x;
    const int tx  = tid & 15;
    const int ty  = tid >> 4;
    const int m0  = blockIdx.y * 128;
    const int n0  = blockIdx.x * 128;

    // A-load map: rows m0+ar and m0+ar+64, 4 k-floats at ak
    const int ar = tid >> 2;            // 0..63
    const int ak = (tid & 3) * 4;       // 0,4,8,12
    // B-load map: k-rows bk and bk+8, 4 n-floats at bn
    const int bk = tid >> 5;            // 0..7
    const int bn = (tid & 31) * 4;      // 0..124

    const float* Aptr0 = A + (size_t)(m0 + ar) * K + ak;
    const float* Aptr1 = A + (size_t)(m0 + ar + 64) * K + ak;
    const float* Bptr0 = Bp + (size_t)bk * N + n0 + bn;
    const float* Bptr1 = Bp + (size_t)(bk + 8) * N + n0 + bn;

    float acc[8][8];
#pragma unroll
    for (int i = 0; i < 8; i++)
#pragma unroll
        for (int j = 0; j < 8; j++) acc[i][j] = 0.f;

    float4 pa0 = *(const float4*)(Aptr0);
    float4 pa1 = *(const float4*)(Aptr1);
    float4 pb0 = *(const float4*)(Bptr0);
    float4 pb1 = *(const float4*)(Bptr1);

    for (int k0 = 0; k0 < K; k0 += 16) {
        As[ak + 0][ar]      = pa0.x;
        As[ak + 1][ar]      = pa0.y;
        As[ak + 2][ar]      = pa0.z;
        As[ak + 3][ar]      = pa0.w;
        As[ak + 0][ar + 64] = pa1.x;
        As[ak + 1][ar + 64] = pa1.y;
        As[ak + 2][ar + 64] = pa1.z;
        As[ak + 3][ar + 64] = pa1.w;
        *(float4*)&Bs[bk][bn]     = pb0;
        *(float4*)&Bs[bk + 8][bn] = pb1;
        __syncthreads();

        if (k0 + 16 < K) {          // prefetch next tile; overlaps compute
            pa0 = *(const float4*)(Aptr0 + k0 + 16);
            pa1 = *(const float4*)(Aptr1 + k0 + 16);
            pb0 = *(const float4*)(Bptr0 + (size_t)(k0 + 16) * N);
            pb1 = *(const float4*)(Bptr1 + (size_t)(k0 + 16) * N);
        }

#pragma unroll
        for (int kk = 0; kk < 16; kk++) {
            float a[8], b[8];
            *(float4*)&a[0] = *(const float4*)&As[kk][ty * 4];
            *(float4*)&a[4] = *(const float4*)&As[kk][ty * 4 + 64];
            *(float4*)&b[0] = *(const float4*)&Bs[kk][tx * 4];
            *(float4*)&b[4] = *(const float4*)&Bs[kk][tx * 4 + 64];
#pragma unroll
            for (int i = 0; i < 8; i++)
#pragma unroll
                for (int j = 0; j < 8; j++)
                    acc[i][j] = fmaf(a[i], b[j], acc[i][j]);
        }
        __syncthreads();
    }

#pragma unroll
    for (int i = 0; i < 8; i++) {
        const int mrow = m0 + ty * 4 + (i & 3) + (i >> 2) * 64;
        const float bv = bias[mrow];
        float4 o0, o1;
        o0.x = acc[i][0] + bv; o0.y = acc[i][1] + bv;
        o0.z = acc[i][2] + bv; o0.w = acc[i][3] + bv;
        o1.x = acc[i][4] + bv; o1.y = acc[i][5] + bv;
        o1.z = acc[i][6] + bv; o1.w = acc[i][7] + bv;
        *(float4*)(Cp + (size_t)mrow * N + n0 + tx * 4)      = o0;
        *(float4*)(Cp + (size_t)mrow * N + n0 + tx * 4 + 64) = o1;
    }
}

// ---------------------------------------------------------------------------
// Fused windowed attention. Grid (D, H/TY, B*HEADS), block 128 = 32(x)*4(y).
// Per dz: stage zero-padded k/v z-slice [HD][YH][XH] in smem; compute all 25
// (dy,dx) scores into registers, one online-softmax rescale per dz, then the
// 32-accumulator output phase.
// ---------------------------------------------------------------------------
#define TY       4
#define XH       36
#define YH       (TY + 2*PADW)        // 8
#define CH_EL    (YH*XH)              // 288
#define SLICE_EL (HD*CH_EL)           // 9216
#define PE_EL    (HD*WS*WS*WS)        // 4000
#define QSM_EL   (HD*128)             // 4096
#define ATTN_SMEM ((2*SLICE_EL + PE_EL + QSM_EL)*4)   // 106,944 B

__global__ __launch_bounds__(128)
void attn3d_kernel(const float* __restrict__ qkv,
                   const float* __restrict__ pos_embed,
                   float* __restrict__ attn_out)
{
    extern __shared__ float smem[];
    float* ksm = smem;                       // [HD][YH][XH]
    float* vsm = smem + SLICE_EL;
    float* pes = smem + 2 * SLICE_EL;        // [HD][125]
    float* qsm = smem + 2 * SLICE_EL + PE_EL; // [HD][128] per-thread column

    const int tid  = threadIdx.x;
    const int tx   = tid & 31;
    const int ty   = tid >> 5;
    const int z    = blockIdx.x;
    const int y0   = blockIdx.y * TY;
    const int bh   = blockIdx.z;
    const int b    = bh / HEADS;
    const int head = bh % HEADS;

    const float* qbase = qkv + ((size_t)b * (3 * CC) + head * HD) * SSP;
    const float* kbase = qbase + (size_t)CC * SSP;
    const float* vbase = qbase + (size_t)(2 * CC) * SSP;

    for (int i = tid; i < PE_EL; i += 128) pes[i] = pos_embed[i];

    const int y = y0 + ty;
    const size_t svox = (size_t)z * (HH * WW) + y * WW + tx;
#pragma unroll 8
    for (int hd = 0; hd < HD; hd++)
        qsm[hd * 128 + tid] = qbase[(size_t)hd * SSP + svox];

    // Staging geometry: this thread covers positions tid, tid+128, tid+256
    // of each 288-element channel slice. Precompute once.
    int g0, g1, g2;
    bool ib0, ib1, ib2;
    {
        int p  = tid;
        int yy = p / XH, xx = p - yy * XH;
        int ys = y0 + yy - PADW, xs = xx - PADW;
        ib0 = (ys >= 0) & (ys < HH) & (xs >= 0) & (xs < WW);
        g0  = ys * WW + xs;
        p  = tid + 128;
        yy = p / XH; xx = p - yy * XH;
        ys = y0 + yy - PADW; xs = xx - PADW;
        ib1 = (ys >= 0) & (ys < HH) & (xs >= 0) & (xs < WW);
        g1  = ys * WW + xs;
        p  = tid + 256;
        yy = p / XH; xx = p - yy * XH;
        ys = y0 + yy - PADW; xs = xx - PADW;
        ib2 = (p < CH_EL) & (ys >= 0) & (ys < HH) & (xs >= 0) & (xs < WW);
        g2  = ys * WW + xs;
    }
    const bool pv2 = (tid < CH_EL - 256);   // tid < 32

    float m = -1e30f, l = 0.f;
    float out[HD];
#pragma unroll
    for (int hd = 0; hd < HD; hd++) out[hd] = 0.f;

    const int base = ty * XH + tx;

    for (int dz = 0; dz < WS; dz++) {
        const int zs = z + dz - PADW;

        // ---- stage k/v slice ----
        if (zs >= 0 && zs < DD) {
            const float* kb = kbase + (size_t)zs * (HH * WW);
            const float* vb = vbase + (size_t)zs * (HH * WW);
#pragma unroll 4
            for (int ch = 0; ch < HD; ch++) {
                const ptrdiff_t co = (ptrdiff_t)ch * SSP;
                const int so = ch * CH_EL;
                ksm[so + tid]       = ib0 ? kb[co + g0] : 0.f;
                vsm[so + tid]       = ib0 ? vb[co + g0] : 0.f;
                ksm[so + tid + 128] = ib1 ? kb[co + g1] : 0.f;
                vsm[so + tid + 128] = ib1 ? vb[co + g1] : 0.f;
                if (pv2) {
                    ksm[so + tid + 256] = ib2 ? kb[co + g2] : 0.f;
                    vsm[so + tid + 256] = ib2 ? vb[co + g2] : 0.f;
                }
            }
        } else {
            for (int i = tid; i < SLICE_EL; i += 128) { ksm[i] = 0.f; vsm[i] = 0.f; }
        }
        __syncthreads();

        // ---- score phase: 25 independent accumulators ----
        float s[25];
#pragma unroll
        for (int j = 0; j < 25; j++) s[j] = 0.f;

        const float* peb = pes + dz * 25;
        for (int hd = 0; hd < HD; hd++) {
            const float  qh = qsm[hd * 128 + tid];
            const float* kr = ksm + hd * CH_EL + base;
            const float* pe = peb + hd * 125;           // broadcast reads
#pragma unroll
            for (int dy = 0; dy < 5; dy++)
#pragma unroll
                for (int dx = 0; dx < 5; dx++)
                    s[dy * 5 + dx] = fmaf(qh, kr[dy * XH + dx] + pe[dy * 5 + dx],
                                          s[dy * 5 + dx]);
        }

        // ---- online softmax (one rescale per dz) ----
        float mx = -1e30f;
#pragma unroll
        for (int j = 0; j < 25; j++) { s[j] *= SCALE; mx = fmaxf(mx, s[j]); }
        const float nm = fmaxf(m, mx);
        const float c  = __expf(m - nm);
        m = nm;
        l *= c;
#pragma unroll
        for (int hd = 0; hd < HD; hd++) out[hd] *= c;
        float ps = 0.f;
#pragma unroll
        for (int j = 0; j < 25; j++) { s[j] = __expf(s[j] - nm); ps += s[j]; }
        l += ps;

        // ---- output phase: 32 independent accumulators ----
        const float* vb2 = vsm + base;
#pragma unroll
        for (int dy = 0; dy < 5; dy++)
#pragma unroll
            for (int dx = 0; dx < 5; dx++) {
                const float  pj = s[dy * 5 + dx];
                const float* vr = vb2 + dy * XH + dx;
#pragma unroll
                for (int hd = 0; hd < HD; hd++)
                    out[hd] = fmaf(pj, vr[hd * CH_EL], out[hd]);
            }
        __syncthreads();
    }

    const float inv = 1.f / l;
    float* ob = attn_out + ((size_t)b * CC + head * HD) * SSP + svox;
#pragma unroll
    for (int hd = 0; hd < HD; hd++) ob[(size_t)hd * SSP] = out[hd] * inv;
}

// ---------------------------------------------------------------------------
// Launch
// ---------------------------------------------------------------------------
extern "C" void kernel_launch(void* const* d_in, const int* in_sizes, int n_in,
                              void* d_out, int out_size)
{
    const float* x         = (const float*)d_in[0];
    const float* w_qkv     = (const float*)d_in[1];
    const float* b_qkv     = (const float*)d_in[2];
    const float* w_proj    = (const float*)d_in[3];
    const float* b_proj    = (const float*)d_in[4];
    const float* pos_embed = (const float*)d_in[5];
    float* outp = (float*)d_out;

    float* qkv;  cudaGetSymbolAddress((void**)&qkv,  g_qkv);
    float* attn; cudaGetSymbolAddress((void**)&attn, g_attn);

    // 1) QKV projection: M=1152, N=32768, K=384, batch 2
    {
        dim3 grid(SSP / 128, (3 * CC) / 128, BB);
        sgemm128<<<grid, 256>>>(w_qkv, x, b_qkv, qkv,
                                3 * CC, SSP, CC,
                                (size_t)CC * SSP, (size_t)(3 * CC) * SSP);
    }

    // 2) Fused windowed attention
    {
        cudaFuncSetAttribute(attn3d_kernel,
                             cudaFuncAttributeMaxDynamicSharedMemorySize,
                             ATTN_SMEM);
        dim3 grid(DD, HH / TY, BB * HEADS);
        attn3d_kernel<<<grid, 128, ATTN_SMEM>>>(qkv, pos_embed, attn);
    }

    // 3) Output projection: M=384, N=32768, K=384, batch 2
    {
        dim3 grid(SSP / 128, CC / 128, BB);
        sgemm128<<<grid, 256>>>(w_proj, attn, b_proj, outp,
                                CC, SSP, CC,
                                (size_t)CC * SSP, (size_t)CC * SSP);
    }
}

// round 6
// speedup vs baseline: 1.0000x; 1.0000x over previous
#include <cuda_runtime.h>
#include <cstdint>
#include <cstddef>

// Problem constants
#define BB      2
#define CC      384
#define DD      32
#define HH      32
#define WW      32
#define HEADS   12
#define HD      32
#define WS      5
#define PADW    2
#define SSP     (DD*HH*WW)           // 32768
#define SCALE   0.17677669529663687f // 32^-0.5

// Scratch (device globals; allocation in kernel_launch is forbidden)
__device__ float g_qkv[(size_t)BB * 3 * CC * SSP];
__device__ float g_attn[(size_t)BB * CC * SSP];

// ---------------------------------------------------------------------------
// SGEMM: C[b][m][n] = sum_k A[m][k]*B[b][k][n] + bias[m]
// 128x128x16 tile, 256 threads, 8x8 microtile, LDG prefetch over compute.
// All dims divide evenly (M in {1152,384}, N=32768, K=384).
// ---------------------------------------------------------------------------
__global__ __launch_bounds__(256)
void sgemm128(const float* __restrict__ A, const float* __restrict__ B,
              const float* __restrict__ bias, float* __restrict__ C,
              int M, int N, int K, size_t strideB, size_t strideC)
{
    __shared__ __align__(16) float As[16][132];   // padded: 2-way store conflict max
    __shared__ __align__(16) float Bs[16][128];

    const float* Bp = B + (size_t)blockIdx.z * strideB;
    float*       Cp = C + (size_t)blockIdx.z * strideC;

    const int tid = threadIdx.x;
    const int tx  = tid & 15;
    const int ty  = tid >> 4;
    const int m0  = blockIdx.y * 128;
    const int n0  = blockIdx.x * 128;

    // A-load map: rows m0+ar and m0+ar+64, 4 k-floats at ak
    const int ar = tid >> 2;            // 0..63
    const int ak = (tid & 3) * 4;       // 0,4,8,12
    // B-load map: k-rows bk and bk+8, 4 n-floats at bn
    const int bk = tid >> 5;            // 0..7
    const int bn = (tid & 31) * 4;      // 0..124

    const float* Aptr0 = A + (size_t)(m0 + ar) * K + ak;
    const float* Aptr1 = A + (size_t)(m0 + ar + 64) * K + ak;
    const float* Bptr0 = Bp + (size_t)bk * N + n0 + bn;
    const float* Bptr1 = Bp + (size_t)(bk + 8) * N + n0 + bn;

    float acc[8][8];
#pragma unroll
    for (int i = 0; i < 8; i++)
#pragma unroll
        for (int j = 0; j < 8; j++) acc[i][j] = 0.f;

    float4 pa0 = *(const float4*)(Aptr0);
    float4 pa1 = *(const float4*)(Aptr1);
    float4 pb0 = *(const float4*)(Bptr0);
    float4 pb1 = *(const float4*)(Bptr1);

    for (int k0 = 0; k0 < K; k0 += 16) {
        As[ak + 0][ar]      = pa0.x;
        As[ak + 1][ar]      = pa0.y;
        As[ak + 2][ar]      = pa0.z;
        As[ak + 3][ar]      = pa0.w;
        As[ak + 0][ar + 64] = pa1.x;
        As[ak + 1][ar + 64] = pa1.y;
        As[ak + 2][ar + 64] = pa1.z;
        As[ak + 3][ar + 64] = pa1.w;
        *(float4*)&Bs[bk][bn]     = pb0;
        *(float4*)&Bs[bk + 8][bn] = pb1;
        __syncthreads();

        if (k0 + 16 < K) {          // prefetch next tile; overlaps compute
            pa0 = *(const float4*)(Aptr0 + k0 + 16);
            pa1 = *(const float4*)(Aptr1 + k0 + 16);
            pb0 = *(const float4*)(Bptr0 + (size_t)(k0 + 16) * N);
            pb1 = *(const float4*)(Bptr1 + (size_t)(k0 + 16) * N);
        }

#pragma unroll
        for (int kk = 0; kk < 16; kk++) {
            float a[8], b[8];
            *(float4*)&a[0] = *(const float4*)&As[kk][ty * 4];
            *(float4*)&a[4] = *(const float4*)&As[kk][ty * 4 + 64];
            *(float4*)&b[0] = *(const float4*)&Bs[kk][tx * 4];
            *(float4*)&b[4] = *(const float4*)&Bs[kk][tx * 4 + 64];
#pragma unroll
            for (int i = 0; i < 8; i++)
#pragma unroll
                for (int j = 0; j < 8; j++)
                    acc[i][j] = fmaf(a[i], b[j], acc[i][j]);
        }
        __syncthreads();
    }

#pragma unroll
    for (int i = 0; i < 8; i++) {
        const int mrow = m0 + ty * 4 + (i & 3) + (i >> 2) * 64;
        const float bv = bias[mrow];
        float4 o0, o1;
        o0.x = acc[i][0] + bv; o0.y = acc[i][1] + bv;
        o0.z = acc[i][2] + bv; o0.w = acc[i][3] + bv;
        o1.x = acc[i][4] + bv; o1.y = acc[i][5] + bv;
        o1.z = acc[i][6] + bv; o1.w = acc[i][7] + bv;
        *(float4*)(Cp + (size_t)mrow * N + n0 + tx * 4)      = o0;
        *(float4*)(Cp + (size_t)mrow * N + n0 + tx * 4 + 64) = o1;
    }
}

// ---------------------------------------------------------------------------
// Fused windowed attention. Grid (D, H/TY, B*HEADS), block 128 = 32(x)*4(y).
// Per dz: stage zero-padded k/v z-slice [HD][YH][XH] in smem; compute all 25
// (dy,dx) scores into registers, one online-softmax rescale per dz, then the
// 32-accumulator output phase.
// ---------------------------------------------------------------------------
#define TY       4
#define XH       36
#define YH       (TY + 2*PADW)        // 8
#define CH_EL    (YH*XH)              // 288
#define SLICE_EL (HD*CH_EL)           // 9216
#define PE_EL    (HD*WS*WS*WS)        // 4000
#define QSM_EL   (HD*128)             // 4096
#define ATTN_SMEM ((2*SLICE_EL + PE_EL + QSM_EL)*4)   // 106,944 B

__global__ __launch_bounds__(128)
void attn3d_kernel(const float* __restrict__ qkv,
                   const float* __restrict__ pos_embed,
                   float* __restrict__ attn_out)
{
    extern __shared__ float smem[];
    float* ksm = smem;                       // [HD][YH][XH]
    float* vsm = smem + SLICE_EL;
    float* pes = smem + 2 * SLICE_EL;        // [HD][125]
    float* qsm = smem + 2 * SLICE_EL + PE_EL; // [HD][128] per-thread column

    const int tid  = threadIdx.x;
    const int tx   = tid & 31;
    const int ty   = tid >> 5;
    const int z    = blockIdx.x;
    const int y0   = blockIdx.y * TY;
    const int bh   = blockIdx.z;
    const int b    = bh / HEADS;
    const int head = bh % HEADS;

    const float* qbase = qkv + ((size_t)b * (3 * CC) + head * HD) * SSP;
    const float* kbase = qbase + (size_t)CC * SSP;
    const float* vbase = qbase + (size_t)(2 * CC) * SSP;

    for (int i = tid; i < PE_EL; i += 128) pes[i] = pos_embed[i];

    const int y = y0 + ty;
    const size_t svox = (size_t)z * (HH * WW) + y * WW + tx;
#pragma unroll 8
    for (int hd = 0; hd < HD; hd++)
        qsm[hd * 128 + tid] = qbase[(size_t)hd * SSP + svox];

    // Staging geometry: this thread covers positions tid, tid+128, tid+256
    // of each 288-element channel slice. Precompute once.
    int g0, g1, g2;
    bool ib0, ib1, ib2;
    {
        int p  = tid;
        int yy = p / XH, xx = p - yy * XH;
        int ys = y0 + yy - PADW, xs = xx - PADW;
        ib0 = (ys >= 0) & (ys < HH) & (xs >= 0) & (xs < WW);
        g0  = ys * WW + xs;
        p  = tid + 128;
        yy = p / XH; xx = p - yy * XH;
        ys = y0 + yy - PADW; xs = xx - PADW;
        ib1 = (ys >= 0) & (ys < HH) & (xs >= 0) & (xs < WW);
        g1  = ys * WW + xs;
        p  = tid + 256;
        yy = p / XH; xx = p - yy * XH;
        ys = y0 + yy - PADW; xs = xx - PADW;
        ib2 = (p < CH_EL) & (ys >= 0) & (ys < HH) & (xs >= 0) & (xs < WW);
        g2  = ys * WW + xs;
    }
    const bool pv2 = (tid < CH_EL - 256);   // tid < 32

    float m = -1e30f, l = 0.f;
    float out[HD];
#pragma unroll
    for (int hd = 0; hd < HD; hd++) out[hd] = 0.f;

    const int base = ty * XH + tx;

    for (int dz = 0; dz < WS; dz++) {
        const int zs = z + dz - PADW;

        // ---- stage k/v slice ----
        if (zs >= 0 && zs < DD) {
            const float* kb = kbase + (size_t)zs * (HH * WW);
            const float* vb = vbase + (size_t)zs * (HH * WW);
#pragma unroll 4
            for (int ch = 0; ch < HD; ch++) {
                const ptrdiff_t co = (ptrdiff_t)ch * SSP;
                const int so = ch * CH_EL;
                ksm[so + tid]       = ib0 ? kb[co + g0] : 0.f;
                vsm[so + tid]       = ib0 ? vb[co + g0] : 0.f;
                ksm[so + tid + 128] = ib1 ? kb[co + g1] : 0.f;
                vsm[so + tid + 128] = ib1 ? vb[co + g1] : 0.f;
                if (pv2) {
                    ksm[so + tid + 256] = ib2 ? kb[co + g2] : 0.f;
                    vsm[so + tid + 256] = ib2 ? vb[co + g2] : 0.f;
                }
            }
        } else {
            for (int i = tid; i < SLICE_EL; i += 128) { ksm[i] = 0.f; vsm[i] = 0.f; }
        }
        __syncthreads();

        // ---- score phase: 25 independent accumulators ----
        float s[25];
#pragma unroll
        for (int j = 0; j < 25; j++) s[j] = 0.f;

        const float* peb = pes + dz * 25;
        for (int hd = 0; hd < HD; hd++) {
            const float  qh = qsm[hd * 128 + tid];
            const float* kr = ksm + hd * CH_EL + base;
            const float* pe = peb + hd * 125;           // broadcast reads
#pragma unroll
            for (int dy = 0; dy < 5; dy++)
#pragma unroll
                for (int dx = 0; dx < 5; dx++)
                    s[dy * 5 + dx] = fmaf(qh, kr[dy * XH + dx] + pe[dy * 5 + dx],
                                          s[dy * 5 + dx]);
        }

        // ---- online softmax (one rescale per dz) ----
        float mx = -1e30f;
#pragma unroll
        for (int j = 0; j < 25; j++) { s[j] *= SCALE; mx = fmaxf(mx, s[j]); }
        const float nm = fmaxf(m, mx);
        const float c  = __expf(m - nm);
        m = nm;
        l *= c;
#pragma unroll
        for (int hd = 0; hd < HD; hd++) out[hd] *= c;
        float ps = 0.f;
#pragma unroll
        for (int j = 0; j < 25; j++) { s[j] = __expf(s[j] - nm); ps += s[j]; }
        l += ps;

        // ---- output phase: 32 independent accumulators ----
        const float* vb2 = vsm + base;
#pragma unroll
        for (int dy = 0; dy < 5; dy++)
#pragma unroll
            for (int dx = 0; dx < 5; dx++) {
                const float  pj = s[dy * 5 + dx];
                const float* vr = vb2 + dy * XH + dx;
#pragma unroll
                for (int hd = 0; hd < HD; hd++)
                    out[hd] = fmaf(pj, vr[hd * CH_EL], out[hd]);
            }
        __syncthreads();
    }

    const float inv = 1.f / l;
    float* ob = attn_out + ((size_t)b * CC + head * HD) * SSP + svox;
#pragma unroll
    for (int hd = 0; hd < HD; hd++) ob[(size_t)hd * SSP] = out[hd] * inv;
}

// ---------------------------------------------------------------------------
// Launch
// ---------------------------------------------------------------------------
extern "C" void kernel_launch(void* const* d_in, const int* in_sizes, int n_in,
                              void* d_out, int out_size)
{
    const float* x         = (const float*)d_in[0];
    const float* w_qkv     = (const float*)d_in[1];
    const float* b_qkv     = (const float*)d_in[2];
    const float* w_proj    = (const float*)d_in[3];
    const float* b_proj    = (const float*)d_in[4];
    const float* pos_embed = (const float*)d_in[5];
    float* outp = (float*)d_out;

    float* qkv;  cudaGetSymbolAddress((void**)&qkv,  g_qkv);
    float* attn; cudaGetSymbolAddress((void**)&attn, g_attn);

    // 1) QKV projection: M=1152, N=32768, K=384, batch 2
    {
        dim3 grid(SSP / 128, (3 * CC) / 128, BB);
        sgemm128<<<grid, 256>>>(w_qkv, x, b_qkv, qkv,
                                3 * CC, SSP, CC,
                                (size_t)CC * SSP, (size_t)(3 * CC) * SSP);
    }

    // 2) Fused windowed attention
    {
        cudaFuncSetAttribute(attn3d_kernel,
                             cudaFuncAttributeMaxDynamicSharedMemorySize,
                             ATTN_SMEM);
        dim3 grid(DD, HH / TY, BB * HEADS);
        attn3d_kernel<<<grid, 128, ATTN_SMEM>>>(qkv, pos_embed, attn);
    }

    // 3) Output projection: M=384, N=32768, K=384, batch 2
    {
        dim3 grid(SSP / 128, CC / 128, BB);
        sgemm128<<<grid, 256>>>(w_proj, attn, b_proj, outp,
                                CC, SSP, CC,
                                (size_t)CC * SSP, (size_t)CC * SSP);
    }
}

// round 7
// speedup vs baseline: 1.0028x; 1.0028x over previous
#include <cuda_runtime.h>
#include <cstdint>
#include <cstddef>

// Problem constants
#define BB      2
#define CC      384
#define DD      32
#define HH      32
#define WW      32
#define HEADS   12
#define HD      32
#define WS      5
#define PADW    2
#define SSP     (DD*HH*WW)           // 32768
#define SCALE   0.17677669529663687f // 32^-0.5

// Scratch (device globals; allocation in kernel_launch is forbidden)
__device__ float g_qkv[(size_t)BB * 3 * CC * SSP];
__device__ float g_attn[(size_t)BB * CC * SSP];

// ---------------------------------------------------------------------------
// SGEMM: C[b][m][n] = sum_k A[m][k]*B[b][k][n] + bias[m]
// 128x128x16 tile, 256 threads, 8x8 microtile, LDG prefetch over compute.
// All dims divide evenly (M in {1152,384}, N=32768, K=384).
// ---------------------------------------------------------------------------
__global__ __launch_bounds__(256)
void sgemm128(const float* __restrict__ A, const float* __restrict__ B,
              const float* __restrict__ bias, float* __restrict__ C,
              int M, int N, int K, size_t strideB, size_t strideC)
{
    __shared__ __align__(16) float As[16][132];   // padded: 2-way store conflict max
    __shared__ __align__(16) float Bs[16][128];

    const float* Bp = B + (size_t)blockIdx.z * strideB;
    float*       Cp = C + (size_t)blockIdx.z * strideC;

    const int tid = threadIdx.x;
    const int tx  = tid & 15;
    const int ty  = tid >> 4;
    const int m0  = blockIdx.y * 128;
    const int n0  = blockIdx.x * 128;

    // A-load map: rows m0+ar and m0+ar+64, 4 k-floats at ak
    const int ar = tid >> 2;            // 0..63
    const int ak = (tid & 3) * 4;       // 0,4,8,12
    // B-load map: k-rows bk and bk+8, 4 n-floats at bn
    const int bk = tid >> 5;            // 0..7
    const int bn = (tid & 31) * 4;      // 0..124

    const float* Aptr0 = A + (size_t)(m0 + ar) * K + ak;
    const float* Aptr1 = A + (size_t)(m0 + ar + 64) * K + ak;
    const float* Bptr0 = Bp + (size_t)bk * N + n0 + bn;
    const float* Bptr1 = Bp + (size_t)(bk + 8) * N + n0 + bn;

    float acc[8][8];
#pragma unroll
    for (int i = 0; i < 8; i++)
#pragma unroll
        for (int j = 0; j < 8; j++) acc[i][j] = 0.f;

    float4 pa0 = *(const float4*)(Aptr0);
    float4 pa1 = *(const float4*)(Aptr1);
    float4 pb0 = *(const float4*)(Bptr0);
    float4 pb1 = *(const float4*)(Bptr1);

    for (int k0 = 0; k0 < K; k0 += 16) {
        As[ak + 0][ar]      = pa0.x;
        As[ak + 1][ar]      = pa0.y;
        As[ak + 2][ar]      = pa0.z;
        As[ak + 3][ar]      = pa0.w;
        As[ak + 0][ar + 64] = pa1.x;
        As[ak + 1][ar + 64] = pa1.y;
        As[ak + 2][ar + 64] = pa1.z;
        As[ak + 3][ar + 64] = pa1.w;
        *(float4*)&Bs[bk][bn]     = pb0;
        *(float4*)&Bs[bk + 8][bn] = pb1;
        __syncthreads();

        if (k0 + 16 < K) {          // prefetch next tile; overlaps compute
            pa0 = *(const float4*)(Aptr0 + k0 + 16);
            pa1 = *(const float4*)(Aptr1 + k0 + 16);
            pb0 = *(const float4*)(Bptr0 + (size_t)(k0 + 16) * N);
            pb1 = *(const float4*)(Bptr1 + (size_t)(k0 + 16) * N);
        }

#pragma unroll
        for (int kk = 0; kk < 16; kk++) {
            float a[8], b[8];
            *(float4*)&a[0] = *(const float4*)&As[kk][ty * 4];
            *(float4*)&a[4] = *(const float4*)&As[kk][ty * 4 + 64];
            *(float4*)&b[0] = *(const float4*)&Bs[kk][tx * 4];
            *(float4*)&b[4] = *(const float4*)&Bs[kk][tx * 4 + 64];
#pragma unroll
            for (int i = 0; i < 8; i++)
#pragma unroll
                for (int j = 0; j < 8; j++)
                    acc[i][j] = fmaf(a[i], b[j], acc[i][j]);
        }
        __syncthreads();
    }

#pragma unroll
    for (int i = 0; i < 8; i++) {
        const int mrow = m0 + ty * 4 + (i & 3) + (i >> 2) * 64;
        const float bv = bias[mrow];
        float4 o0, o1;
        o0.x = acc[i][0] + bv; o0.y = acc[i][1] + bv;
        o0.z = acc[i][2] + bv; o0.w = acc[i][3] + bv;
        o1.x = acc[i][4] + bv; o1.y = acc[i][5] + bv;
        o1.z = acc[i][6] + bv; o1.w = acc[i][7] + bv;
        *(float4*)(Cp + (size_t)mrow * N + n0 + tx * 4)      = o0;
        *(float4*)(Cp + (size_t)mrow * N + n0 + tx * 4 + 64) = o1;
    }
}

// ---------------------------------------------------------------------------
// Fused windowed attention. Grid (D, H/TY, B*HEADS), block 128 = 32(x)*4(y).
// Per dz: stage zero-padded k/v z-slice [HD][YH][XH] in smem; compute all 25
// (dy,dx) scores into registers, one online-softmax rescale per dz, then the
// 32-accumulator output phase.
// ---------------------------------------------------------------------------
#define TY       4
#define XH       36
#define YH       (TY + 2*PADW)        // 8
#define CH_EL    (YH*XH)              // 288
#define SLICE_EL (HD*CH_EL)           // 9216
#define PE_EL    (HD*WS*WS*WS)        // 4000
#define QSM_EL   (HD*128)             // 4096
#define ATTN_SMEM ((2*SLICE_EL + PE_EL + QSM_EL)*4)   // 106,944 B

__global__ __launch_bounds__(128)
void attn3d_kernel(const float* __restrict__ qkv,
                   const float* __restrict__ pos_embed,
                   float* __restrict__ attn_out)
{
    extern __shared__ float smem[];
    float* ksm = smem;                       // [HD][YH][XH]
    float* vsm = smem + SLICE_EL;
    float* pes = smem + 2 * SLICE_EL;        // [HD][125]
    float* qsm = smem + 2 * SLICE_EL + PE_EL; // [HD][128] per-thread column

    const int tid  = threadIdx.x;
    const int tx   = tid & 31;
    const int ty   = tid >> 5;
    const int z    = blockIdx.x;
    const int y0   = blockIdx.y * TY;
    const int bh   = blockIdx.z;
    const int b    = bh / HEADS;
    const int head = bh % HEADS;

    const float* qbase = qkv + ((size_t)b * (3 * CC) + head * HD) * SSP;
    const float* kbase = qbase + (size_t)CC * SSP;
    const float* vbase = qbase + (size_t)(2 * CC) * SSP;

    for (int i = tid; i < PE_EL; i += 128) pes[i] = pos_embed[i];

    const int y = y0 + ty;
    const size_t svox = (size_t)z * (HH * WW) + y * WW + tx;
#pragma unroll 8
    for (int hd = 0; hd < HD; hd++)
        qsm[hd * 128 + tid] = qbase[(size_t)hd * SSP + svox];

    // Staging geometry: this thread covers positions tid, tid+128, tid+256
    // of each 288-element channel slice. Precompute once.
    int g0, g1, g2;
    bool ib0, ib1, ib2;
    {
        int p  = tid;
        int yy = p / XH, xx = p - yy * XH;
        int ys = y0 + yy - PADW, xs = xx - PADW;
        ib0 = (ys >= 0) & (ys < HH) & (xs >= 0) & (xs < WW);
        g0  = ys * WW + xs;
        p  = tid + 128;
        yy = p / XH; xx = p - yy * XH;
        ys = y0 + yy - PADW; xs = xx - PADW;
        ib1 = (ys >= 0) & (ys < HH) & (xs >= 0) & (xs < WW);
        g1  = ys * WW + xs;
        p  = tid + 256;
        yy = p / XH; xx = p - yy * XH;
        ys = y0 + yy - PADW; xs = xx - PADW;
        ib2 = (p < CH_EL) & (ys >= 0) & (ys < HH) & (xs >= 0) & (xs < WW);
        g2  = ys * WW + xs;
    }
    const bool pv2 = (tid < CH_EL - 256);   // tid < 32

    float m = -1e30f, l = 0.f;
    float out[HD];
#pragma unroll
    for (int hd = 0; hd < HD; hd++) out[hd] = 0.f;

    const int base = ty * XH + tx;

    for (int dz = 0; dz < WS; dz++) {
        const int zs = z + dz - PADW;

        // ---- stage k/v slice ----
        if (zs >= 0 && zs < DD) {
            const float* kb = kbase + (size_t)zs * (HH * WW);
            const float* vb = vbase + (size_t)zs * (HH * WW);
#pragma unroll 4
            for (int ch = 0; ch < HD; ch++) {
                const ptrdiff_t co = (ptrdiff_t)ch * SSP;
                const int so = ch * CH_EL;
                ksm[so + tid]       = ib0 ? kb[co + g0] : 0.f;
                vsm[so + tid]       = ib0 ? vb[co + g0] : 0.f;
                ksm[so + tid + 128] = ib1 ? kb[co + g1] : 0.f;
                vsm[so + tid + 128] = ib1 ? vb[co + g1] : 0.f;
                if (pv2) {
                    ksm[so + tid + 256] = ib2 ? kb[co + g2] : 0.f;
                    vsm[so + tid + 256] = ib2 ? vb[co + g2] : 0.f;
                }
            }
        } else {
            for (int i = tid; i < SLICE_EL; i += 128) { ksm[i] = 0.f; vsm[i] = 0.f; }
        }
        __syncthreads();

        // ---- score phase: 25 independent accumulators ----
        float s[25];
#pragma unroll
        for (int j = 0; j < 25; j++) s[j] = 0.f;

        const float* peb = pes + dz * 25;
        for (int hd = 0; hd < HD; hd++) {
            const float  qh = qsm[hd * 128 + tid];
            const float* kr = ksm + hd * CH_EL + base;
            const float* pe = peb + hd * 125;           // broadcast reads
#pragma unroll
            for (int dy = 0; dy < 5; dy++)
#pragma unroll
                for (int dx = 0; dx < 5; dx++)
                    s[dy * 5 + dx] = fmaf(qh, kr[dy * XH + dx] + pe[dy * 5 + dx],
                                          s[dy * 5 + dx]);
        }

        // ---- online softmax (one rescale per dz) ----
        float mx = -1e30f;
#pragma unroll
        for (int j = 0; j < 25; j++) { s[j] *= SCALE; mx = fmaxf(mx, s[j]); }
        const float nm = fmaxf(m, mx);
        const float c  = __expf(m - nm);
        m = nm;
        l *= c;
#pragma unroll
        for (int hd = 0; hd < HD; hd++) out[hd] *= c;
        float ps = 0.f;
#pragma unroll
        for (int j = 0; j < 25; j++) { s[j] = __expf(s[j] - nm); ps += s[j]; }
        l += ps;

        // ---- output phase: 32 independent accumulators ----
        const float* vb2 = vsm + base;
#pragma unroll
        for (int dy = 0; dy < 5; dy++)
#pragma unroll
            for (int dx = 0; dx < 5; dx++) {
                const float  pj = s[dy * 5 + dx];
                const float* vr = vb2 + dy * XH + dx;
#pragma unroll
                for (int hd = 0; hd < HD; hd++)
                    out[hd] = fmaf(pj, vr[hd * CH_EL], out[hd]);
            }
        __syncthreads();
    }

    const float inv = 1.f / l;
    float* ob = attn_out + ((size_t)b * CC + head * HD) * SSP + svox;
#pragma unroll
    for (int hd = 0; hd < HD; hd++) ob[(size_t)hd * SSP] = out[hd] * inv;
}

// ---------------------------------------------------------------------------
// Launch
// ---------------------------------------------------------------------------
extern "C" void kernel_launch(void* const* d_in, const int* in_sizes, int n_in,
                              void* d_out, int out_size)
{
    const float* x         = (const float*)d_in[0];
    const float* w_qkv     = (const float*)d_in[1];
    const float* b_qkv     = (const float*)d_in[2];
    const float* w_proj    = (const float*)d_in[3];
    const float* b_proj    = (const float*)d_in[4];
    const float* pos_embed = (const float*)d_in[5];
    float* outp = (float*)d_out;

    float* qkv;  cudaGetSymbolAddress((void**)&qkv,  g_qkv);
    float* attn; cudaGetSymbolAddress((void**)&attn, g_attn);

    // 1) QKV projection: M=1152, N=32768, K=384, batch 2
    {
        dim3 grid(SSP / 128, (3 * CC) / 128, BB);
        sgemm128<<<grid, 256>>>(w_qkv, x, b_qkv, qkv,
                                3 * CC, SSP, CC,
                                (size_t)CC * SSP, (size_t)(3 * CC) * SSP);
    }

    // 2) Fused windowed attention
    {
        cudaFuncSetAttribute(attn3d_kernel,
                             cudaFuncAttributeMaxDynamicSharedMemorySize,
                             ATTN_SMEM);
        dim3 grid(DD, HH / TY, BB * HEADS);
        attn3d_kernel<<<grid, 128, ATTN_SMEM>>>(qkv, pos_embed, attn);
    }

    // 3) Output projection: M=384, N=32768, K=384, batch 2
    {
        dim3 grid(SSP / 128, CC / 128, BB);
        sgemm128<<<grid, 256>>>(w_proj, attn, b_proj, outp,
                                CC, SSP, CC,
                                (size_t)CC * SSP, (size_t)CC * SSP);
    }
}